// round 10
// baseline (speedup 1.0000x reference)
#include <cuda_runtime.h>
#include <math.h>

#define NV 3
#define NA 4
#define NN 50000
#define NC 128
#define NVA    (NV * NA)                 // 12
#define CHUNKS 128
#define ROWS   ((NN + CHUNKS - 1) / CHUNKS)   // 391

// u[12*128] followed by t[12]; zeroed via one memsetAsync per launch.
__device__ __align__(16) float g_ut[NVA * NC + NVA];

// -----------------------------------------------------------------------------
// Kernel A: column sums over an n-chunk + per-block epilogue that folds the
// partial sum straight into u (atomicAdd). No separate prep kernel needed:
//   u[va,:] = sum_blocks (partial_s/N) @ W[v],  t[va] = sum_blocks (partial_s/N).b[v]
// grid = (12, 128), block = 256 (8 row-warps x 32 lanes, float4 per lane)
// -----------------------------------------------------------------------------
__global__ __launch_bounds__(256) void sum_u_kernel(const float* __restrict__ x,
                                                    const float* __restrict__ W,
                                                    const float* __restrict__ b) {
    const int va   = blockIdx.x;                 // v*NA + a
    const int n0   = blockIdx.y * ROWS;
    const int n1   = min(n0 + ROWS, NN);
    const int lane = threadIdx.x & 31;
    const int warp = threadIdx.x >> 5;

    const float4* __restrict__ xb =
        reinterpret_cast<const float4*>(x) + (size_t)va * NN * 32;

    // Streaming column-sum with DEFAULT caching: leaves chunk tails in L2
    // for the combine pass.
    float4 acc = make_float4(0.f, 0.f, 0.f, 0.f);
    #pragma unroll 4
    for (int n = n0 + warp; n < n1; n += 8) {
        float4 v = xb[(size_t)n * 32 + lane];
        acc.x += v.x; acc.y += v.y; acc.z += v.z; acc.w += v.w;
    }

    __shared__ float4 red[256];
    __shared__ float  sh_s[NC];
    red[threadIdx.x] = acc;
    __syncthreads();

    if (warp == 0) {
        float4 tot = red[lane];
        #pragma unroll
        for (int g = 1; g < 8; ++g) {
            float4 v = red[g * 32 + lane];
            tot.x += v.x; tot.y += v.y; tot.z += v.z; tot.w += v.w;
        }
        const float inv = 1.0f / (float)NN;
        sh_s[lane * 4 + 0] = tot.x * inv;
        sh_s[lane * 4 + 1] = tot.y * inv;
        sh_s[lane * 4 + 2] = tot.z * inv;
        sh_s[lane * 4 + 3] = tot.w * inv;
    }
    __syncthreads();

    // Epilogue: partial_u[c] = sum_d sh_s[d] * W[v][d][c]  (split d over 2 halves)
    const int v    = va >> 2;
    const int c    = threadIdx.x & 127;
    const int half = threadIdx.x >> 7;
    const float* __restrict__ Wv = W + (size_t)v * NC * NC;

    float au = 0.f;
    const int d0 = half * 64;
    #pragma unroll 16
    for (int d = d0; d < d0 + 64; ++d) au += sh_s[d] * __ldg(&Wv[d * NC + c]);
    atomicAdd(&g_ut[va * NC + c], au);

    // partial_t = sh_s . b[v]
    if (warp == 0) {
        const float* __restrict__ bv = b + v * NC;
        float tb = 0.f;
        #pragma unroll
        for (int d = lane; d < NC; d += 32) tb += sh_s[d] * bv[d];
        #pragma unroll
        for (int o = 16; o; o >>= 1) tb += __shfl_xor_sync(0xFFFFFFFFu, tb, o);
        if (lane == 0) atomicAdd(&g_ut[NVA * NC + va], tb);
    }
}

// -----------------------------------------------------------------------------
// Kernel B: per node (a,n): scores -> tanh -> softmax over views -> combine.
// Mirrors pass-1 chunking and walks each chunk in DESCENDING n so first-wave
// warps start on the chunk tails pass 1 left resident in L2. Reads use __ldcs
// (evict-first: misses don't displace resident lines), writes use __stcs.
// grid = (256, 4): blockIdx.x = chunk*2 + half, block = 256 (8 warps)
// -----------------------------------------------------------------------------
__global__ __launch_bounds__(256) void combine_kernel(const float* __restrict__ x,
                                                      float* __restrict__ out) {
    const int a    = blockIdx.y;
    const int c    = blockIdx.x >> 1;
    const int half = blockIdx.x & 1;
    const int lane = threadIdx.x & 31;
    const int warp = threadIdx.x >> 5;

    const float4* ub = reinterpret_cast<const float4*>(g_ut);
    const float4 u0 = ub[(size_t)(0 * NA + a) * 32 + lane];
    const float4 u1 = ub[(size_t)(1 * NA + a) * 32 + lane];
    const float4 u2 = ub[(size_t)(2 * NA + a) * 32 + lane];
    const float t0 = g_ut[NVA * NC + 0 * NA + a];
    const float t1 = g_ut[NVA * NC + 1 * NA + a];
    const float t2 = g_ut[NVA * NC + 2 * NA + a];

    const size_t vstride = (size_t)NA * NN * 32;   // float4 units per view
    const float4* __restrict__ xb =
        reinterpret_cast<const float4*>(x) + (size_t)a * NN * 32;
    float4* __restrict__ ob =
        reinterpret_cast<float4*>(out) + (size_t)a * NN * 32;

    const int n0 = c * ROWS;
    const int n1 = min(n0 + ROWS, NN);
    const int j  = half * 8 + warp;                // 0..15 sub-warps per chunk

    for (int n = n1 - 1 - j; n >= n0; n -= 16) {
        const size_t base = (size_t)n * 32 + lane;
        const float4 x0 = __ldcs(&xb[base]);
        const float4 x1 = __ldcs(&xb[base + vstride]);
        const float4 x2 = __ldcs(&xb[base + 2 * vstride]);

        float p0 = x0.x * u0.x + x0.y * u0.y + x0.z * u0.z + x0.w * u0.w;
        float p1 = x1.x * u1.x + x1.y * u1.y + x1.z * u1.z + x1.w * u1.w;
        float p2 = x2.x * u2.x + x2.y * u2.y + x2.z * u2.z + x2.w * u2.w;

        #pragma unroll
        for (int o = 16; o; o >>= 1) {
            p0 += __shfl_xor_sync(0xFFFFFFFFu, p0, o);
            p1 += __shfl_xor_sync(0xFFFFFFFFu, p1, o);
            p2 += __shfl_xor_sync(0xFFFFFFFFu, p2, o);
        }
        p0 += t0; p1 += t1; p2 += t2;

        // tanh via MUFU, then exp for the 3-way softmax
        const float th0 = __fdividef(2.f, 1.f + __expf(-2.f * p0)) - 1.f;
        const float th1 = __fdividef(2.f, 1.f + __expf(-2.f * p1)) - 1.f;
        const float th2 = __fdividef(2.f, 1.f + __expf(-2.f * p2)) - 1.f;
        const float e0 = __expf(th0);
        const float e1 = __expf(th1);
        const float e2 = __expf(th2);
        const float inv = __fdividef(1.f, e0 + e1 + e2);
        const float w0 = e0 * inv, w1 = e1 * inv, w2 = e2 * inv;

        float4 o;
        o.x = w0 * x0.x + w1 * x1.x + w2 * x2.x;
        o.y = w0 * x0.y + w1 * x1.y + w2 * x2.y;
        o.z = w0 * x0.z + w1 * x1.z + w2 * x2.z;
        o.w = w0 * x0.w + w1 * x1.w + w2 * x2.w;
        __stcs(&ob[base], o);
    }
}

// -----------------------------------------------------------------------------
extern "C" void kernel_launch(void* const* d_in, const int* in_sizes, int n_in,
                              void* d_out, int out_size) {
    const float* x  = (const float*)d_in[0];   // [V,A,N,C]
    const float* Wm = (const float*)d_in[1];   // [V,C,C]
    const float* b  = (const float*)d_in[2];   // [V,C]
    float* out = (float*)d_out;                // [A,N,C]
    (void)in_sizes; (void)n_in; (void)out_size;

    void* p = nullptr;
    cudaGetSymbolAddress(&p, g_ut);
    cudaMemsetAsync(p, 0, sizeof(float) * (NVA * NC + NVA));

    sum_u_kernel<<<dim3(NVA, CHUNKS), 256>>>(x, Wm, b);
    combine_kernel<<<dim3(2 * CHUNKS, NA), 256>>>(x, out);
}

// round 11
// speedup vs baseline: 1.1199x; 1.1199x over previous
#include <cuda_runtime.h>
#include <math.h>

#define NV 3
#define NA 4
#define NN 50000
#define NC 128
#define NVA (NV * NA)

// Scratch; g_s zeroed each launch via memsetAsync.
__device__ __align__(16) float g_s[NVA * NC];
__device__ __align__(16) float g_u[NVA * NC];
__device__ float g_t[NVA];

// -----------------------------------------------------------------------------
// Kernel 1: column sums over the node dimension (round-4 exact: 49.6us, 79% DRAM)
// grid = (12, 128), block = 256 (8 row-warps x 32 lanes, float4 per lane)
// -----------------------------------------------------------------------------
__global__ __launch_bounds__(256) void col_sum_kernel(const float* __restrict__ x) {
    const int va      = blockIdx.x;
    const int nchunks = gridDim.y;
    const int rows    = (NN + nchunks - 1) / nchunks;
    const int n0      = blockIdx.y * rows;
    const int n1      = min(n0 + rows, NN);

    const int lane = threadIdx.x & 31;
    const int w    = threadIdx.x >> 5;

    const float4* __restrict__ xb =
        reinterpret_cast<const float4*>(x) + (size_t)va * NN * 32;

    float4 acc = make_float4(0.f, 0.f, 0.f, 0.f);
    #pragma unroll 4
    for (int n = n0 + w; n < n1; n += 8) {
        float4 val = xb[(size_t)n * 32 + lane];
        acc.x += val.x; acc.y += val.y; acc.z += val.z; acc.w += val.w;
    }

    __shared__ float4 sm[256];
    sm[threadIdx.x] = acc;
    __syncthreads();

    if (threadIdx.x < 32) {
        float4 tot = sm[threadIdx.x];
        #pragma unroll
        for (int g = 1; g < 8; g++) {
            float4 val = sm[g * 32 + threadIdx.x];
            tot.x += val.x; tot.y += val.y; tot.z += val.z; tot.w += val.w;
        }
        float* dst = g_s + va * NC + threadIdx.x * 4;
        atomicAdd(dst + 0, tot.x);
        atomicAdd(dst + 1, tot.y);
        atomicAdd(dst + 2, tot.z);
        atomicAdd(dst + 3, tot.w);
    }
}

// -----------------------------------------------------------------------------
// Kernel 2 (tiny): u[v,a,:] = (s/N) @ W[v],  t[v,a] = (s/N) . b[v]
// Widened to 48 blocks for lower latency: grid (12,4), block 128.
// Block (va, q) computes u columns [q*32, q*32+32): 4 d-groups x 32 columns.
// -----------------------------------------------------------------------------
__global__ __launch_bounds__(128) void prep_kernel(const float* __restrict__ Wm,
                                                   const float* __restrict__ b) {
    const int va = blockIdx.x;
    const int q  = blockIdx.y;
    const int v  = va >> 2;
    const int cl = threadIdx.x & 31;     // column within the 32-slice
    const int dg = threadIdx.x >> 5;     // d-group 0..3
    const int c  = q * 32 + cl;

    __shared__ float sh_s[NC];
    __shared__ float part[4][32];

    if (threadIdx.x < NC)
        sh_s[threadIdx.x] = g_s[va * NC + threadIdx.x] * (1.0f / (float)NN);
    __syncthreads();

    const float* __restrict__ Wv = Wm + (size_t)v * NC * NC;
    float acc = 0.f;
    #pragma unroll 8
    for (int d = dg * 32; d < dg * 32 + 32; ++d)
        acc += sh_s[d] * __ldg(&Wv[d * NC + c]);
    part[dg][cl] = acc;
    __syncthreads();

    if (dg == 0)
        g_u[va * NC + c] = (part[0][cl] + part[1][cl]) + (part[2][cl] + part[3][cl]);

    if (q == 0 && dg == 1) {   // one warp per va computes t
        const float* __restrict__ bv = b + v * NC;
        float tb = 0.f;
        #pragma unroll
        for (int d = cl; d < NC; d += 32) tb += sh_s[d] * bv[d];
        #pragma unroll
        for (int o = 16; o; o >>= 1) tb += __shfl_xor_sync(0xFFFFFFFFu, tb, o);
        if (cl == 0) g_t[va] = tb;
    }
}

// -----------------------------------------------------------------------------
// Kernel 3: scores -> tanh -> softmax over views -> combine.
// TWO nodes per warp-iteration: 6 loads in flight, 6 interleaved shuffle
// chains, 2 interleaved softmax chains -> latency hiding via ILP.
// grid = (625, 4), block = 256 (8 warps). Warp m handles node pairs
// (m + i*10000, m + i*10000 + 5000) for i = 0..4.
// -----------------------------------------------------------------------------
__global__ __launch_bounds__(256) void combine_kernel(const float* __restrict__ x,
                                                      float* __restrict__ out) {
    const int a    = blockIdx.y;
    const int lane = threadIdx.x & 31;
    const int warp = threadIdx.x >> 5;

    const float4* ub = reinterpret_cast<const float4*>(g_u);
    const float4 u0 = ub[(size_t)(0 * NA + a) * 32 + lane];
    const float4 u1 = ub[(size_t)(1 * NA + a) * 32 + lane];
    const float4 u2 = ub[(size_t)(2 * NA + a) * 32 + lane];
    const float t0 = g_t[0 * NA + a];
    const float t1 = g_t[1 * NA + a];
    const float t2 = g_t[2 * NA + a];

    const size_t vstride = (size_t)NA * NN * 32;   // float4 units per view
    const float4* __restrict__ xb =
        reinterpret_cast<const float4*>(x) + (size_t)a * NN * 32;
    float4* __restrict__ ob =
        reinterpret_cast<float4*>(out) + (size_t)a * NN * 32;

    const int m = blockIdx.x * 8 + warp;           // 0..4999

    #pragma unroll
    for (int i = 0; i < 5; ++i) {
        const int na = m + i * 10000;
        const int nb = na + 5000;
        const size_t ba = (size_t)na * 32 + lane;
        const size_t bb = (size_t)nb * 32 + lane;

        // 6 independent loads
        const float4 xa0 = xb[ba];
        const float4 xb0 = xb[bb];
        const float4 xa1 = xb[ba + vstride];
        const float4 xb1 = xb[bb + vstride];
        const float4 xa2 = xb[ba + 2 * vstride];
        const float4 xb2 = xb[bb + 2 * vstride];

        float pa0 = xa0.x * u0.x + xa0.y * u0.y + xa0.z * u0.z + xa0.w * u0.w;
        float pa1 = xa1.x * u1.x + xa1.y * u1.y + xa1.z * u1.z + xa1.w * u1.w;
        float pa2 = xa2.x * u2.x + xa2.y * u2.y + xa2.z * u2.z + xa2.w * u2.w;
        float pb0 = xb0.x * u0.x + xb0.y * u0.y + xb0.z * u0.z + xb0.w * u0.w;
        float pb1 = xb1.x * u1.x + xb1.y * u1.y + xb1.z * u1.z + xb1.w * u1.w;
        float pb2 = xb2.x * u2.x + xb2.y * u2.y + xb2.z * u2.z + xb2.w * u2.w;

        // 6 interleaved 5-deep shuffle chains
        #pragma unroll
        for (int o = 16; o; o >>= 1) {
            pa0 += __shfl_xor_sync(0xFFFFFFFFu, pa0, o);
            pb0 += __shfl_xor_sync(0xFFFFFFFFu, pb0, o);
            pa1 += __shfl_xor_sync(0xFFFFFFFFu, pa1, o);
            pb1 += __shfl_xor_sync(0xFFFFFFFFu, pb1, o);
            pa2 += __shfl_xor_sync(0xFFFFFFFFu, pa2, o);
            pb2 += __shfl_xor_sync(0xFFFFFFFFu, pb2, o);
        }
        pa0 += t0; pa1 += t1; pa2 += t2;
        pb0 += t0; pb1 += t1; pb2 += t2;

        // tanh = 2/(1+e^{-2p}) - 1 (MUFU), then exp; two interleaved chains
        const float ea0 = __expf(__fdividef(2.f, 1.f + __expf(-2.f * pa0)) - 1.f);
        const float eb0 = __expf(__fdividef(2.f, 1.f + __expf(-2.f * pb0)) - 1.f);
        const float ea1 = __expf(__fdividef(2.f, 1.f + __expf(-2.f * pa1)) - 1.f);
        const float eb1 = __expf(__fdividef(2.f, 1.f + __expf(-2.f * pb1)) - 1.f);
        const float ea2 = __expf(__fdividef(2.f, 1.f + __expf(-2.f * pa2)) - 1.f);
        const float eb2 = __expf(__fdividef(2.f, 1.f + __expf(-2.f * pb2)) - 1.f);

        const float inva = __fdividef(1.f, ea0 + ea1 + ea2);
        const float invb = __fdividef(1.f, eb0 + eb1 + eb2);
        const float wa0 = ea0 * inva, wa1 = ea1 * inva, wa2 = ea2 * inva;
        const float wb0 = eb0 * invb, wb1 = eb1 * invb, wb2 = eb2 * invb;

        float4 oa, obv;
        oa.x = wa0 * xa0.x + wa1 * xa1.x + wa2 * xa2.x;
        oa.y = wa0 * xa0.y + wa1 * xa1.y + wa2 * xa2.y;
        oa.z = wa0 * xa0.z + wa1 * xa1.z + wa2 * xa2.z;
        oa.w = wa0 * xa0.w + wa1 * xa1.w + wa2 * xa2.w;
        obv.x = wb0 * xb0.x + wb1 * xb1.x + wb2 * xb2.x;
        obv.y = wb0 * xb0.y + wb1 * xb1.y + wb2 * xb2.y;
        obv.z = wb0 * xb0.z + wb1 * xb1.z + wb2 * xb2.z;
        obv.w = wb0 * xb0.w + wb1 * xb1.w + wb2 * xb2.w;
        __stcs(&ob[ba], oa);
        __stcs(&ob[bb], obv);
    }
}

// -----------------------------------------------------------------------------
extern "C" void kernel_launch(void* const* d_in, const int* in_sizes, int n_in,
                              void* d_out, int out_size) {
    const float* x  = (const float*)d_in[0];   // [V,A,N,C]
    const float* Wm = (const float*)d_in[1];   // [V,C,C]
    const float* b  = (const float*)d_in[2];   // [V,C]
    float* out = (float*)d_out;                // [A,N,C]
    (void)in_sizes; (void)n_in; (void)out_size;

    void* p = nullptr;
    cudaGetSymbolAddress(&p, g_s);
    cudaMemsetAsync(p, 0, NVA * NC * sizeof(float));

    col_sum_kernel<<<dim3(NVA, 128), 256>>>(x);
    prep_kernel<<<dim3(NVA, 4), 128>>>(Wm, b);
    combine_kernel<<<dim3(625, NA), 256>>>(x, out);
}